// round 15
// baseline (speedup 1.0000x reference)
#include <cuda_runtime.h>
#include <cuda_fp16.h>
#include <cstdint>

// y = gather_perm(x @ Wv) @ Wo^T   (softmax rowsum == 1 collapse, validated R1)
// tcgen05 unavailable (harness targets sm_103, no 'a') => mma.sync path.
// Both GEMMs pinned at the legacy-HMMA wall (~16.9 cyc/HMMA worst-SM, G1==G2;
// R14's "G1 gap" was a stale-data accounting error). GEMMs frozen (R12 form).
// R15: persistent single-wave prep (296 blocks = 2x148, grid-stride convert,
//      no 2nd wave / no wave-transition) + carveout hint to avoid the
//      smem-config flip at the prep->G1 boundary.

#define MTOT 4096
#define DD   1024
#define BK   64
#define KSB  144                 // smem row stride bytes: conflict-free ldmatrix
#define STG_MAT  (128 * KSB)     // 18432 B per matrix tile
#define OFF_B    STG_MAT
#define STG_BYTES (2 * STG_MAT)  // 36864 B / stage
#define NSTAGE   3
#define SMEM_SZ  (NSTAGE * STG_BYTES)  // 110592 B ; 2 CTAs/SM
#define NCHUNK   (DD / BK)       // 16

#define PREP_BLOCKS 296          // 2 x 148 SMs: exactly one wave at 2 CTA/SM
#define XN4  (MTOT * DD / 8)     // 524288 uint4 outputs for x
#define WON4 (DD * DD / 8)       // 131072 uint4 outputs for Wo

__device__ __half g_xh[MTOT * DD];
__device__ __half g_wvt[DD * DD];
__device__ __half g_wo[DD * DD];
__device__ __half g_vh[MTOT * DD];

// ------------------------------------------------------------------ asm utils
static __device__ __forceinline__ uint32_t smem_u32(const void* p) {
    uint32_t a;
    asm("{ .reg .u64 t; cvta.to.shared.u64 t, %1; cvt.u32.u64 %0, t; }" : "=r"(a) : "l"(p));
    return a;
}
#define CP16(s, g) \
    asm volatile("cp.async.cg.shared.global [%0], [%1], 16;" :: "r"(s), "l"(g))
#define CP_COMMIT() asm volatile("cp.async.commit_group;")
#define CP_WAIT1()  asm volatile("cp.async.wait_group 1;")

#define LDSM4(r, addr) \
    asm volatile("ldmatrix.sync.aligned.m8n8.x4.shared.b16 {%0,%1,%2,%3}, [%4];" \
                 : "=r"((r)[0]), "=r"((r)[1]), "=r"((r)[2]), "=r"((r)[3]) : "r"(addr))

#define MMA(d, a, b0, b1) \
    asm volatile("mma.sync.aligned.m16n8k16.row.col.f32.f16.f16.f32 " \
                 "{%0,%1,%2,%3}, {%4,%5,%6,%7}, {%8,%9}, {%0,%1,%2,%3};" \
                 : "+f"((d)[0]), "+f"((d)[1]), "+f"((d)[2]), "+f"((d)[3]) \
                 : "r"((a)[0]), "r"((a)[1]), "r"((a)[2]), "r"((a)[3]), "r"(b0), "r"(b1))

// ------------------------------------------------------------------ GEMM (frozen R12)
// MODE 0: V = x @ WvT^T  (A = g_xh [m][k], B = g_wvt [n][k]) -> g_vh (fp16)
// MODE 1: out = gather(V) @ Wo^T (A gathered from g_vh, B = g_wo) -> fp32
template<int MODE>
__global__ void __launch_bounds__(128, 2)
gemm_hmma(float* __restrict__ outp) {
    extern __shared__ char smem[];
    const uint32_t sb = smem_u32(smem);

    const int tid  = threadIdx.x;
    const int lane = tid & 31, wid = tid >> 5;
    const int bm = blockIdx.y * 128;
    const int bn = blockIdx.x * 128;

    const __half* A_ = (MODE == 0) ? g_xh  : g_vh;
    const __half* B_ = (MODE == 0) ? g_wvt : g_wo;

    // gather constants (MODE 1): with BK=64 chunks, k>>6 == c exactly.
    const int boff = (bm >> 11) << 11;          // b * 2048
    const int hoff = ((bm & 2047) >> 7) * 64;   // h * 64

    // ---- global -> smem stage loader: 128 threads, 16 CP16 per thread
    const int seg  = tid & 7;        // 16B segment of 128B row
    const int row0 = tid >> 3;       // 0..15

    auto issue = [&](int c) {
        const uint32_t sbase = sb + (uint32_t)(c % NSTAGE) * STG_BYTES;
#pragma unroll
        for (int i = 0; i < 8; i++) {
            const int row = row0 + 16 * i;
            size_t aoff;
            if (MODE == 0) {
                aoff = (size_t)(bm + row) * DD + c * BK + seg * 8;
            } else {
                aoff = (size_t)(boff + row * 16 + c) * DD + hoff + seg * 8;
            }
            const size_t bo = (size_t)(bn + row) * DD + c * BK + seg * 8;
            CP16(sbase + row * KSB + seg * 16,         A_ + aoff);
            CP16(sbase + OFF_B + row * KSB + seg * 16, B_ + bo);
        }
        CP_COMMIT();
    };

    // ---- warp tiling: 2(m) x 2(n) warps of 64x64
    const int warp_m = (wid >> 1) * 64;
    const int warp_n = (wid & 1) * 64;
    const int lr = lane & 15;            // ldmatrix row within 16
    const int lcb = (lane >> 4) * 16;    // ldmatrix k-half byte offset

    float acc[4][8][4];
#pragma unroll
    for (int mt = 0; mt < 4; mt++)
#pragma unroll
        for (int j = 0; j < 8; j++)
#pragma unroll
            for (int q = 0; q < 4; q++) acc[mt][j][q] = 0.f;

    issue(0);
    issue(1);

    for (int c = 0; c < NCHUNK; c++) {
        CP_WAIT1();          // in-order groups: group c complete
        __syncthreads();
        // stage (c+2)%3 == (c-1)%3 was last read in compute(c-1); all warps
        // passed the barrier above -> overwrite safe.
        if (c + 2 < NCHUNK) issue(c + 2);

        const uint32_t sbase = sb + (uint32_t)(c % NSTAGE) * STG_BYTES;
#pragma unroll
        for (int kk = 0; kk < 4; kk++) {
            const uint32_t kb = kk * 32 + lcb;  // k byte offset within 128B row

            uint32_t aa[4][4], bb[4][4];
#pragma unroll
            for (int mt = 0; mt < 4; mt++)
                LDSM4(aa[mt], sbase + (warp_m + mt * 16 + lr) * KSB + kb);
#pragma unroll
            for (int nt = 0; nt < 4; nt++)
                LDSM4(bb[nt], sbase + OFF_B + (warp_n + nt * 16 + lr) * KSB + kb);

#pragma unroll
            for (int mt = 0; mt < 4; mt++)
#pragma unroll
                for (int nt = 0; nt < 4; nt++) {
                    MMA(acc[mt][2 * nt],     aa[mt], bb[nt][0], bb[nt][2]);
                    MMA(acc[mt][2 * nt + 1], aa[mt], bb[nt][1], bb[nt][3]);
                }
        }
    }

    // ---- epilogue (fragment layout: d0,d1 -> row lane>>2, d2,d3 -> +8)
#pragma unroll
    for (int mt = 0; mt < 4; mt++) {
        const int m0 = bm + warp_m + mt * 16 + (lane >> 2);
#pragma unroll
        for (int j = 0; j < 8; j++) {
            const int n0 = bn + warp_n + j * 8 + (lane & 3) * 2;
            const float* d = acc[mt][j];
            if (MODE == 0) {
#pragma unroll
                for (int half_ = 0; half_ < 2; half_++) {
                    const size_t o = (size_t)(m0 + 8 * half_) * DD + n0;
                    *(__half2*)&g_vh[o] =
                        __floats2half2_rn(d[2 * half_], d[2 * half_ + 1]);
                }
            } else {
#pragma unroll
                for (int half_ = 0; half_ < 2; half_++) {
                    const size_t o = (size_t)(m0 + 8 * half_) * DD + n0;
                    *(float2*)&outp[o] = make_float2(d[2 * half_], d[2 * half_ + 1]);
                }
            }
        }
    }
}

// ------------------------------------------------------------------ prep
static __device__ __forceinline__ uint32_t h2u(__half2 h) {
    return *reinterpret_cast<uint32_t*>(&h);
}
static __device__ __forceinline__ uint4 pack8(float4 a, float4 b) {
    uint4 o;
    o.x = h2u(__floats2half2_rn(a.x, a.y));
    o.y = h2u(__floats2half2_rn(a.z, a.w));
    o.z = h2u(__floats2half2_rn(b.x, b.y));
    o.w = h2u(__floats2half2_rn(b.z, b.w));
    return o;
}

// Persistent single-wave prep: 296 blocks (one wave at 2 CTA/SM).
// Blocks [0,256) first do one 64x64 WvT transpose tile, then ALL blocks
// grid-stride over the combined x (+Wo) fp32->fp16 conversion range.
__global__ void __launch_bounds__(256, 2)
k_prep(const float* __restrict__ x,
       const float* __restrict__ Wv,
       const float* __restrict__ Wo) {
    const int blk = blockIdx.x, tid = threadIdx.x;

    if (blk < 256) {
        // WvT[n][k] = Wv[k][n]; tile: k-base (blk&15)*64, n-base (blk>>4)*64
        const int tk = (blk & 15) * 64, tn = (blk >> 4) * 64;
        __shared__ float tt[64][65];
#pragma unroll
        for (int i = 0; i < 16; i++) {
            const int idx = tid + 256 * i;
            const int r = idx >> 6, cc = idx & 63;
            tt[r][cc] = Wv[(size_t)(tk + r) * DD + tn + cc];
        }
        __syncthreads();
        const int nl   = tid >> 2;           // 0..63 local n
        const int kseg = (tid & 3) * 16;     // k segment base
        uint32_t w[8];
#pragma unroll
        for (int p = 0; p < 8; p++)
            w[p] = h2u(__floats2half2_rn(tt[kseg + 2 * p][nl], tt[kseg + 2 * p + 1][nl]));
        uint4* dst = (uint4*)&g_wvt[(size_t)(tn + nl) * DD + tk + kseg];
        dst[0] = make_uint4(w[0], w[1], w[2], w[3]);
        dst[1] = make_uint4(w[4], w[5], w[6], w[7]);
    }

    // grid-stride conversion over [0, XN4): x, [XN4, XN4+WON4): Wo
    const int total  = XN4 + WON4;                 // 655360 uint4 outputs
    const int stride = PREP_BLOCKS * 256;
    for (int j = blk * 256 + tid; j < total; j += stride) {
        if (j < XN4) {
            const float4* src = (const float4*)x;
            float4 a = src[2 * j], b = src[2 * j + 1];
            ((uint4*)g_xh)[j] = pack8(a, b);
        } else {
            const int jo = j - XN4;
            const float4* src = (const float4*)Wo;
            float4 a = src[2 * jo], b = src[2 * jo + 1];
            ((uint4*)g_wo)[jo] = pack8(a, b);
        }
    }
}

// ------------------------------------------------------------------ launch
// inputs: x, mask, Wq, Wk, Wv, Wo -> fp32 out [B,T,D]
extern "C" void kernel_launch(void* const* d_in, const int* in_sizes, int n_in,
                              void* d_out, int out_size) {
    const float* x  = (const float*)d_in[0];
    const float* Wv = (const float*)d_in[4];
    const float* Wo = (const float*)d_in[5];
    float* out = (float*)d_out;

    cudaFuncSetAttribute(gemm_hmma<0>, cudaFuncAttributeMaxDynamicSharedMemorySize, SMEM_SZ);
    cudaFuncSetAttribute(gemm_hmma<1>, cudaFuncAttributeMaxDynamicSharedMemorySize, SMEM_SZ);
    // pre-match the GEMM's smem-heavy carveout to avoid reconfig at prep->G1
    cudaFuncSetAttribute(k_prep, cudaFuncAttributePreferredSharedMemoryCarveout, 100);

    k_prep<<<PREP_BLOCKS, 256>>>(x, Wv, Wo);

    dim3 grid(DD / 128, MTOT / 128);   // (8, 32) = 256 CTAs
    gemm_hmma<0><<<grid, 128, SMEM_SZ>>>(nullptr);
    gemm_hmma<1><<<grid, 128, SMEM_SZ>>>(out);
}